// round 1
// baseline (speedup 1.0000x reference)
#include <cuda_runtime.h>
#include <cuda_bf16.h>
#include <cstdint>

#define B_ROWS   512
#define N_FEATS  100000
#define D_DIM    512
#define C_CLS    1854
#define TOPK     10

// Scratch (device globals: allocation-free per harness rules)
__device__ float g_sim[(size_t)B_ROWS * N_FEATS];   // 204.8 MB
__device__ int   g_topk[B_ROWS * TOPK];

// ---------------------------------------------------------------------------
// GEMM: sim[m][n] = sum_k y_pred[m][k] * feats[n][k]   (NT, both K-major)
// 128x128 block tile, BK=16, 256 threads, 8x8 per thread.
// Normalization of y_pred skipped: ranking invariant to positive row scale.
// ---------------------------------------------------------------------------
__global__ void __launch_bounds__(256) gemm_nt_kernel(const float* __restrict__ A,
                                                      const float* __restrict__ Bm) {
    const int bm = blockIdx.y * 128;
    const int bn = blockIdx.x * 128;
    __shared__ float As[16][128];
    __shared__ float Bs[16][128];
    const int tid = threadIdx.x;
    const int tx = tid & 15;   // 16 thread cols
    const int ty = tid >> 4;   // 16 thread rows

    float acc[8][8];
#pragma unroll
    for (int i = 0; i < 8; i++)
#pragma unroll
        for (int j = 0; j < 8; j++) acc[i][j] = 0.f;

    for (int k0 = 0; k0 < D_DIM; k0 += 16) {
#pragma unroll
        for (int l = 0; l < 2; l++) {
            int i   = tid + l * 256;       // 0..511
            int row = i >> 2;              // 0..127
            int c4  = (i & 3) << 2;        // 0,4,8,12
            float4 a = *(const float4*)(A + (size_t)(bm + row) * D_DIM + k0 + c4);
            As[c4 + 0][row] = a.x; As[c4 + 1][row] = a.y;
            As[c4 + 2][row] = a.z; As[c4 + 3][row] = a.w;
            int n = bn + row;
            float4 b = make_float4(0.f, 0.f, 0.f, 0.f);
            if (n < N_FEATS)
                b = *(const float4*)(Bm + (size_t)n * D_DIM + k0 + c4);
            Bs[c4 + 0][row] = b.x; Bs[c4 + 1][row] = b.y;
            Bs[c4 + 2][row] = b.z; Bs[c4 + 3][row] = b.w;
        }
        __syncthreads();
#pragma unroll
        for (int k = 0; k < 16; k++) {
            float ar[8], br[8];
#pragma unroll
            for (int i = 0; i < 8; i++) ar[i] = As[k][ty * 8 + i];
#pragma unroll
            for (int j = 0; j < 8; j++) br[j] = Bs[k][tx * 8 + j];
#pragma unroll
            for (int i = 0; i < 8; i++)
#pragma unroll
                for (int j = 0; j < 8; j++) acc[i][j] += ar[i] * br[j];
        }
        __syncthreads();
    }

#pragma unroll
    for (int i = 0; i < 8; i++) {
        int m = bm + ty * 8 + i;
        float* crow = g_sim + (size_t)m * N_FEATS;
#pragma unroll
        for (int j = 0; j < 8; j += 4) {
            int n = bn + tx * 8 + j;
            if (n + 3 < N_FEATS) {
                *(float4*)(crow + n) = make_float4(acc[i][j], acc[i][j + 1],
                                                   acc[i][j + 2], acc[i][j + 3]);
            } else {
#pragma unroll
                for (int q = 0; q < 4; q++)
                    if (n + q < N_FEATS) crow[n + q] = acc[i][j + q];
            }
        }
    }
}

// ---------------------------------------------------------------------------
// Top-10 per row. Tie-break: lower index wins (matches stable argsort).
// ---------------------------------------------------------------------------
__device__ __forceinline__ bool better(float v, int j, float v2, int j2) {
    return v > v2 || (v == v2 && j < j2);
}

__device__ __forceinline__ void insert10(float (&tv)[TOPK], int (&ti)[TOPK],
                                         float v, int j) {
    if (!better(v, j, tv[TOPK - 1], ti[TOPK - 1])) return;
    bool b[TOPK];
#pragma unroll
    for (int p = 0; p < TOPK; p++) b[p] = better(v, j, tv[p], ti[p]);
#pragma unroll
    for (int p = TOPK - 1; p >= 1; p--) {
        if (b[p]) {
            if (b[p - 1]) { tv[p] = tv[p - 1]; ti[p] = ti[p - 1]; }
            else          { tv[p] = v;         ti[p] = j;         }
        }
    }
    if (b[0]) { tv[0] = v; ti[0] = j; }
}

#define TK_THREADS 256
__global__ void __launch_bounds__(TK_THREADS) topk_kernel() {
    const int row = blockIdx.x;
    const float* s = g_sim + (size_t)row * N_FEATS;
    const int tid = threadIdx.x;

    float tv[TOPK]; int ti[TOPK];
#pragma unroll
    for (int p = 0; p < TOPK; p++) { tv[p] = -__int_as_float(0x7f800000); ti[p] = 0x7fffffff; }

    for (int j = tid; j < N_FEATS; j += TK_THREADS)
        insert10(tv, ti, s[j], j);

    __shared__ float sv[TK_THREADS * TOPK];
    __shared__ int   si[TK_THREADS * TOPK];
    __shared__ float sv2[32 * TOPK];
    __shared__ int   si2[32 * TOPK];
#pragma unroll
    for (int p = 0; p < TOPK; p++) { sv[tid * TOPK + p] = tv[p]; si[tid * TOPK + p] = ti[p]; }
    __syncthreads();

    // Stage B: warp 0, 32 lanes each merge 80 candidates
    if (tid < 32) {
#pragma unroll
        for (int p = 0; p < TOPK; p++) { tv[p] = -__int_as_float(0x7f800000); ti[p] = 0x7fffffff; }
        const int per = (TK_THREADS * TOPK) / 32;  // 80
        for (int c = tid * per; c < (tid + 1) * per; c++)
            insert10(tv, ti, sv[c], si[c]);
#pragma unroll
        for (int p = 0; p < TOPK; p++) { sv2[tid * TOPK + p] = tv[p]; si2[tid * TOPK + p] = ti[p]; }
    }
    __syncthreads();

    // Stage C: thread 0 merges 320 -> final 10
    if (tid == 0) {
#pragma unroll
        for (int p = 0; p < TOPK; p++) { tv[p] = -__int_as_float(0x7f800000); ti[p] = 0x7fffffff; }
        for (int c = 0; c < 32 * TOPK; c++)
            insert10(tv, ti, sv2[c], si2[c]);
#pragma unroll
        for (int p = 0; p < TOPK; p++) g_topk[row * TOPK + p] = ti[p];
    }
}

// ---------------------------------------------------------------------------
// Zero + scatter
// ---------------------------------------------------------------------------
__global__ void zero_kernel(float4* __restrict__ out, int n4) {
    int i = blockIdx.x * blockDim.x + threadIdx.x;
    if (i < n4) out[i] = make_float4(0.f, 0.f, 0.f, 0.f);
}

__global__ void scatter_kernel(const int* __restrict__ y, float* __restrict__ out) {
    int row = blockIdx.x;
    int t = threadIdx.x;
    if (t < TOPK) {
        int idx = g_topk[row * TOPK + t];
        int cls = y[idx];
        out[(size_t)row * C_CLS + cls] = 1.0f;
    }
}

// ---------------------------------------------------------------------------
extern "C" void kernel_launch(void* const* d_in, const int* in_sizes, int n_in,
                              void* d_out, int out_size) {
    const float* y_pred = (const float*)d_in[0];  // [512, 512]
    const float* feats  = (const float*)d_in[1];  // [100000, 512]
    const int*   y      = (const int*)d_in[2];    // [100000]
    float* out = (float*)d_out;                   // [512, 1854]

    dim3 ggrid((N_FEATS + 127) / 128, B_ROWS / 128);  // (782, 4)
    gemm_nt_kernel<<<ggrid, 256>>>(y_pred, feats);

    topk_kernel<<<B_ROWS, TK_THREADS>>>();

    int n4 = out_size / 4;  // 949248 % 4 == 0
    zero_kernel<<<(n4 + 255) / 256, 256>>>((float4*)out, n4);

    scatter_kernel<<<B_ROWS, 32>>>(y, out);
}

// round 3
// speedup vs baseline: 1.8033x; 1.8033x over previous
#include <cuda_runtime.h>
#include <cuda_bf16.h>
#include <cstdint>

#define N_FEATS 100000
#define B_ROWS  512
#define D_DIM   512
#define C_CLS   1854
#define TOPK    10

#define KC      32                  // K elems per chunk
#define NCH     (D_DIM / KC)        // 16 chunks
#define BUF_STRIDE 65536            // per-stage smem bytes
#define SMEM_TOTAL (2 * BUF_STRIDE) // 128 KB
#define OFF_AHI 0
#define OFF_ALO 16384
#define OFF_BHI 32768
#define OFF_BLO 49152

__device__ float g_sim[(size_t)B_ROWS * N_FEATS];   // 204.8 MB scratch
__device__ int   g_topk[B_ROWS * TOPK];

static __device__ __forceinline__ uint32_t smem_u32(const void* p) {
    uint32_t a;
    asm("{ .reg .u64 t; cvta.to.shared.u64 t, %1; cvt.u32.u64 %0, t; }" : "=r"(a) : "l"(p));
    return a;
}
static __device__ __forceinline__ void ldsm4(uint32_t (&r)[4], uint32_t addr) {
    asm volatile("ldmatrix.sync.aligned.m8n8.x4.shared.b16 {%0,%1,%2,%3}, [%4];"
                 : "=r"(r[0]), "=r"(r[1]), "=r"(r[2]), "=r"(r[3]) : "r"(addr));
}
static __device__ __forceinline__ void mma16816(float (&d)[4], const uint32_t (&a)[4],
                                                const uint32_t* b) {
    asm volatile(
        "mma.sync.aligned.m16n8k16.row.col.f32.bf16.bf16.f32 "
        "{%0,%1,%2,%3}, {%4,%5,%6,%7}, {%8,%9}, {%0,%1,%2,%3};"
        : "+f"(d[0]), "+f"(d[1]), "+f"(d[2]), "+f"(d[3])
        : "r"(a[0]), "r"(a[1]), "r"(a[2]), "r"(a[3]), "r"(b[0]), "r"(b[1]));
}

// fp32x4 -> bf16 hi/lo, swizzled store. off = r*128 + q4*8 (pre-swizzle byte offset)
static __device__ __forceinline__ void cvt_store(char* hi, char* lo, int r, int q4, float4 v) {
    __nv_bfloat162 h01 = __floats2bfloat162_rn(v.x, v.y);
    __nv_bfloat162 h23 = __floats2bfloat162_rn(v.z, v.w);
    __nv_bfloat162 l01 = __floats2bfloat162_rn(v.x - __low2float(h01), v.y - __high2float(h01));
    __nv_bfloat162 l23 = __floats2bfloat162_rn(v.z - __low2float(h23), v.w - __high2float(h23));
    uint32_t off = (uint32_t)r * 128 + ((((q4 >> 1) ^ (r & 7))) << 4) + (q4 & 1) * 8;
    *(uint2*)(hi + off) = make_uint2(*(uint32_t*)&h01, *(uint32_t*)&h23);
    *(uint2*)(lo + off) = make_uint2(*(uint32_t*)&l01, *(uint32_t*)&l23);
}

// ---------------------------------------------------------------------------
// GEMM: sim = y_pred @ feats^T, split-bf16 HMMA (hh + hl + lh), fp32 accum.
// CTA tile 128x128, 8 warps (2m x 4n), warp tile 64x32, double-buffered KC=32.
// ---------------------------------------------------------------------------
extern __shared__ char dsm[];

__global__ void __launch_bounds__(256, 1) gemm_hmma(const float* __restrict__ A,
                                                    const float* __restrict__ F) {
    const int mg = blockIdx.x;          // 0..3
    const int nt = blockIdx.y;          // 0..781
    const int tid = threadIdx.x;
    const int lane = tid & 31, w = tid >> 5;
    const int wm = (w >> 2) * 64;       // warp m offset in tile
    const int wn = (w & 3) * 32;        // warp n offset in tile
    const uint32_t sb = smem_u32(dsm);

    float acc[4][4][4];
#pragma unroll
    for (int i = 0; i < 4; i++)
#pragma unroll
        for (int j = 0; j < 4; j++)
#pragma unroll
            for (int q = 0; q < 4; q++) acc[i][j][q] = 0.f;

    // Global load assignment: thread -> (row r_ld, float4 quads (tid&1)*4 + i)
    const int r_ld = tid >> 1;
    const float* Aptr = A + (size_t)(mg * 128 + r_ld) * D_DIM + (tid & 1) * 16;
    const int nB = nt * 128 + r_ld;
    const float* Fptr = F + (size_t)nB * D_DIM + (tid & 1) * 16;
    const bool bValid = nB < N_FEATS;

    float4 stg[8];

#define LDG_CHUNK(c)                                                              \
    do {                                                                          \
        _Pragma("unroll") for (int i = 0; i < 4; i++)                             \
            stg[i] = *(const float4*)(Aptr + (c) * KC + i * 4);                   \
        _Pragma("unroll") for (int i = 0; i < 4; i++)                             \
            stg[4 + i] = bValid ? *(const float4*)(Fptr + (c) * KC + i * 4)       \
                                : make_float4(0.f, 0.f, 0.f, 0.f);                \
    } while (0)

#define STS_CHUNK(buf)                                                            \
    do {                                                                          \
        char* base = dsm + (buf) * BUF_STRIDE;                                    \
        _Pragma("unroll") for (int i = 0; i < 4; i++)                             \
            cvt_store(base + OFF_AHI, base + OFF_ALO, r_ld, (tid & 1) * 4 + i,    \
                      stg[i]);                                                    \
        _Pragma("unroll") for (int i = 0; i < 4; i++)                             \
            cvt_store(base + OFF_BHI, base + OFF_BLO, r_ld, (tid & 1) * 4 + i,    \
                      stg[4 + i]);                                                \
    } while (0)

    // Precompute ldmatrix lane geometry
    // A frags: matrices (rows 0-7 | 8-15) x (k-chunk lo | hi)
    const int rA_base = wm + ((lane >> 3) & 1) * 8 + (lane & 7);
    const int a_c4 = lane >> 4;           // adds to 16B-chunk index
    // B frags: matrices (n 0-7, c0),(n 0-7, c1),(n 8-15, c0),(n 8-15, c1)
    const int rB_base = wn + ((lane >> 4) & 1) * 8 + (lane & 7);
    const int b_c4 = (lane >> 3) & 1;

    LDG_CHUNK(0);

    for (int c = 0; c < NCH; c++) {
        const int buf = c & 1;
        STS_CHUNK(buf);
        __syncthreads();
        if (c + 1 < NCH) LDG_CHUNK(c + 1);

        const uint32_t bAh = sb + buf * BUF_STRIDE + OFF_AHI;
        const uint32_t bAl = sb + buf * BUF_STRIDE + OFF_ALO;
        const uint32_t bBh = sb + buf * BUF_STRIDE + OFF_BHI;
        const uint32_t bBl = sb + buf * BUF_STRIDE + OFF_BLO;

#pragma unroll
        for (int kh = 0; kh < 2; kh++) {
            uint32_t Ah[4][4], Al[4][4], Bh[2][4], Bl[2][4];
#pragma unroll
            for (int mf = 0; mf < 4; mf++) {
                int r = rA_base + mf * 16;
                int cc = (kh * 2 + a_c4) ^ (r & 7);
                ldsm4(Ah[mf], bAh + r * 128 + (cc << 4));
            }
#pragma unroll
            for (int nf2 = 0; nf2 < 2; nf2++) {
                int r = rB_base + nf2 * 16;
                int cc = (kh * 2 + b_c4) ^ (r & 7);
                ldsm4(Bh[nf2], bBh + r * 128 + (cc << 4));
            }
            // pass hh
#pragma unroll
            for (int mf = 0; mf < 4; mf++)
#pragma unroll
                for (int nf = 0; nf < 4; nf++)
                    mma16816(acc[mf][nf], Ah[mf], &Bh[nf >> 1][(nf & 1) * 2]);
            // pass hl
#pragma unroll
            for (int nf2 = 0; nf2 < 2; nf2++) {
                int r = rB_base + nf2 * 16;
                int cc = (kh * 2 + b_c4) ^ (r & 7);
                ldsm4(Bl[nf2], bBl + r * 128 + (cc << 4));
            }
#pragma unroll
            for (int mf = 0; mf < 4; mf++)
#pragma unroll
                for (int nf = 0; nf < 4; nf++)
                    mma16816(acc[mf][nf], Ah[mf], &Bl[nf >> 1][(nf & 1) * 2]);
            // pass lh
#pragma unroll
            for (int mf = 0; mf < 4; mf++) {
                int r = rA_base + mf * 16;
                int cc = (kh * 2 + a_c4) ^ (r & 7);
                ldsm4(Al[mf], bAl + r * 128 + (cc << 4));
            }
#pragma unroll
            for (int mf = 0; mf < 4; mf++)
#pragma unroll
                for (int nf = 0; nf < 4; nf++)
                    mma16816(acc[mf][nf], Al[mf], &Bh[nf >> 1][(nf & 1) * 2]);
        }
    }

    // Epilogue: direct float2 stores (32B sectors fully used)
    const int mrow = mg * 128 + wm + (lane >> 2);
    const int ncol = nt * 128 + wn + (lane & 3) * 2;
#pragma unroll
    for (int mf = 0; mf < 4; mf++) {
#pragma unroll
        for (int nf = 0; nf < 4; nf++) {
            int n = ncol + nf * 8;
            if (n < N_FEATS) {
                size_t m = (size_t)(mrow + mf * 16);
                *(float2*)(g_sim + m * N_FEATS + n) =
                    make_float2(acc[mf][nf][0], acc[mf][nf][1]);
                *(float2*)(g_sim + (m + 8) * N_FEATS + n) =
                    make_float2(acc[mf][nf][2], acc[mf][nf][3]);
            }
        }
    }
}

// ---------------------------------------------------------------------------
// Top-10 per row (tie-break: lower index, matching stable argsort)
// ---------------------------------------------------------------------------
static __device__ __forceinline__ bool better(float v, int j, float v2, int j2) {
    return v > v2 || (v == v2 && j < j2);
}
static __device__ __forceinline__ void insert10(float (&tv)[TOPK], int (&ti)[TOPK],
                                                float v, int j) {
    if (!better(v, j, tv[TOPK - 1], ti[TOPK - 1])) return;
    bool b[TOPK];
#pragma unroll
    for (int p = 0; p < TOPK; p++) b[p] = better(v, j, tv[p], ti[p]);
#pragma unroll
    for (int p = TOPK - 1; p >= 1; p--) {
        if (b[p]) {
            if (b[p - 1]) { tv[p] = tv[p - 1]; ti[p] = ti[p - 1]; }
            else          { tv[p] = v;         ti[p] = j;         }
        }
    }
    if (b[0]) { tv[0] = v; ti[0] = j; }
}

#define TK_THREADS 256
__global__ void __launch_bounds__(TK_THREADS) topk_kernel() {
    const int row = blockIdx.x;
    const float* s = g_sim + (size_t)row * N_FEATS;
    const int tid = threadIdx.x;

    float tv[TOPK]; int ti[TOPK];
#pragma unroll
    for (int p = 0; p < TOPK; p++) { tv[p] = -__int_as_float(0x7f800000); ti[p] = 0x7fffffff; }

    for (int j = tid; j < N_FEATS; j += TK_THREADS)
        insert10(tv, ti, s[j], j);

    __shared__ float sv[TK_THREADS * TOPK];
    __shared__ int   si[TK_THREADS * TOPK];
    __shared__ float sv2[32 * TOPK];
    __shared__ int   si2[32 * TOPK];
#pragma unroll
    for (int p = 0; p < TOPK; p++) { sv[tid * TOPK + p] = tv[p]; si[tid * TOPK + p] = ti[p]; }
    __syncthreads();

    if (tid < 32) {
#pragma unroll
        for (int p = 0; p < TOPK; p++) { tv[p] = -__int_as_float(0x7f800000); ti[p] = 0x7fffffff; }
        const int per = (TK_THREADS * TOPK) / 32;
        for (int c = tid * per; c < (tid + 1) * per; c++)
            insert10(tv, ti, sv[c], si[c]);
#pragma unroll
        for (int p = 0; p < TOPK; p++) { sv2[tid * TOPK + p] = tv[p]; si2[tid * TOPK + p] = ti[p]; }
    }
    __syncthreads();

    if (tid == 0) {
#pragma unroll
        for (int p = 0; p < TOPK; p++) { tv[p] = -__int_as_float(0x7f800000); ti[p] = 0x7fffffff; }
        for (int c = 0; c < 32 * TOPK; c++)
            insert10(tv, ti, sv2[c], si2[c]);
#pragma unroll
        for (int p = 0; p < TOPK; p++) g_topk[row * TOPK + p] = ti[p];
    }
}

// ---------------------------------------------------------------------------
// Zero + scatter
// ---------------------------------------------------------------------------
__global__ void zero_kernel(float4* __restrict__ out, int n4) {
    int i = blockIdx.x * blockDim.x + threadIdx.x;
    if (i < n4) out[i] = make_float4(0.f, 0.f, 0.f, 0.f);
}
__global__ void scatter_kernel(const int* __restrict__ y, float* __restrict__ out) {
    int row = blockIdx.x;
    int t = threadIdx.x;
    if (t < TOPK) {
        int idx = g_topk[row * TOPK + t];
        int cls = y[idx];
        out[(size_t)row * C_CLS + cls] = 1.0f;
    }
}

// ---------------------------------------------------------------------------
extern "C" void kernel_launch(void* const* d_in, const int* in_sizes, int n_in,
                              void* d_out, int out_size) {
    const float* y_pred = (const float*)d_in[0];  // [512, 512]
    const float* feats  = (const float*)d_in[1];  // [100000, 512]
    const int*   y      = (const int*)d_in[2];    // [100000]
    float* out = (float*)d_out;                   // [512, 1854]

    cudaFuncSetAttribute(gemm_hmma, cudaFuncAttributeMaxDynamicSharedMemorySize, SMEM_TOTAL);

    dim3 ggrid(4, (N_FEATS + 127) / 128);  // (4, 782), m fastest -> B tile L2 reuse x4
    gemm_hmma<<<ggrid, 256, SMEM_TOTAL>>>(y_pred, feats);

    topk_kernel<<<B_ROWS, TK_THREADS>>>();

    int n4 = out_size / 4;
    zero_kernel<<<(n4 + 255) / 256, 256>>>((float4*)out, n4);

    scatter_kernel<<<B_ROWS, 32>>>(y, out);
}

// round 4
// speedup vs baseline: 2.0689x; 1.1473x over previous
#include <cuda_runtime.h>
#include <cuda_bf16.h>
#include <cstdint>

#define N_FEATS 100000
#define B_ROWS  512
#define D_DIM   512
#define C_CLS   1854
#define TOPK    10

#define KC      32                  // K elems per chunk (64B bf16 rows)
#define NCH     (D_DIM / KC)        // 16 chunks
#define NSTAGE  3
#define STAGE_BYTES 32768
#define SMEM_TOTAL (NSTAGE * STAGE_BYTES)   // 96 KB -> 2 CTAs/SM
#define OFF_AH 0
#define OFF_AL 8192
#define OFF_BH 16384
#define OFF_BL 24576

__device__ float g_sim[(size_t)B_ROWS * N_FEATS];          // 204.8 MB
__device__ __nv_bfloat16 g_fhi[(size_t)N_FEATS * D_DIM];   // 102.4 MB
__device__ __nv_bfloat16 g_flo[(size_t)N_FEATS * D_DIM];   // 102.4 MB
__device__ __nv_bfloat16 g_ahi[B_ROWS * D_DIM];
__device__ __nv_bfloat16 g_alo[B_ROWS * D_DIM];
__device__ int g_topk[B_ROWS * TOPK];

static __device__ __forceinline__ uint32_t smem_u32(const void* p) {
    uint32_t a;
    asm("{ .reg .u64 t; cvta.to.shared.u64 t, %1; cvt.u32.u64 %0, t; }" : "=r"(a) : "l"(p));
    return a;
}
static __device__ __forceinline__ void ldsm4(uint32_t (&r)[4], uint32_t addr) {
    asm volatile("ldmatrix.sync.aligned.m8n8.x4.shared.b16 {%0,%1,%2,%3}, [%4];"
                 : "=r"(r[0]), "=r"(r[1]), "=r"(r[2]), "=r"(r[3]) : "r"(addr));
}
static __device__ __forceinline__ void mma16816(float (&d)[4], const uint32_t (&a)[4],
                                                const uint32_t* b) {
    asm volatile(
        "mma.sync.aligned.m16n8k16.row.col.f32.bf16.bf16.f32 "
        "{%0,%1,%2,%3}, {%4,%5,%6,%7}, {%8,%9}, {%0,%1,%2,%3};"
        : "+f"(d[0]), "+f"(d[1]), "+f"(d[2]), "+f"(d[3])
        : "r"(a[0]), "r"(a[1]), "r"(a[2]), "r"(a[3]), "r"(b[0]), "r"(b[1]));
}
static __device__ __forceinline__ void cp16(uint32_t dst, const void* src, uint32_t sz) {
    asm volatile("cp.async.cg.shared.global [%0], [%1], 16, %2;"
                 :: "r"(dst), "l"(src), "r"(sz) : "memory");
}

// ---------------------------------------------------------------------------
// Pre-convert: fp32 -> (bf16 hi, bf16 lo)
// ---------------------------------------------------------------------------
__global__ void cvt_kernel(const float* __restrict__ src, __nv_bfloat16* __restrict__ hi,
                           __nv_bfloat16* __restrict__ lo, int n4) {
    int i = blockIdx.x * blockDim.x + threadIdx.x;
    if (i >= n4) return;
    float4 v = ((const float4*)src)[i];
    __nv_bfloat162 h01 = __floats2bfloat162_rn(v.x, v.y);
    __nv_bfloat162 h23 = __floats2bfloat162_rn(v.z, v.w);
    __nv_bfloat162 l01 = __floats2bfloat162_rn(v.x - __low2float(h01), v.y - __high2float(h01));
    __nv_bfloat162 l23 = __floats2bfloat162_rn(v.z - __low2float(h23), v.w - __high2float(h23));
    ((uint2*)hi)[i] = make_uint2(*(uint32_t*)&h01, *(uint32_t*)&h23);
    ((uint2*)lo)[i] = make_uint2(*(uint32_t*)&l01, *(uint32_t*)&l23);
}

// ---------------------------------------------------------------------------
// GEMM mainloop: cp.async 3-stage, split-bf16 HMMA (hh + hl + lh)
// ---------------------------------------------------------------------------
extern __shared__ char dsm[];

static __device__ __forceinline__ void issue_stage(uint32_t sbase, int c, int mg, int nt,
                                                   int tid) {
    const uint32_t stage = sbase + (c % NSTAGE) * STAGE_BYTES;
#pragma unroll
    for (int j = 0; j < 8; j++) {
        int id = tid + j * 256;
        int mat = id >> 9;          // 0:Ah 1:Al 2:Bh 3:Bl
        int rem = id & 511;
        int row = rem >> 2;
        int cc = rem & 3;
        uint32_t dst = stage + mat * 8192 + row * 64 + ((cc ^ ((row >> 1) & 3)) << 4);
        uint32_t sz = 16;
        const __nv_bfloat16* src;
        if (mat < 2) {
            src = (mat == 0 ? g_ahi : g_alo) + (size_t)(mg * 128 + row) * D_DIM + c * KC + cc * 8;
        } else {
            int n = nt * 128 + row;
            if (n >= N_FEATS) { sz = 0; n = 0; }
            src = (mat == 2 ? g_fhi : g_flo) + (size_t)n * D_DIM + c * KC + cc * 8;
        }
        cp16(dst, src, sz);
    }
    asm volatile("cp.async.commit_group;" ::: "memory");
}

__global__ void __launch_bounds__(256, 2) gemm_hmma(void) {
    const int mg = blockIdx.x;          // 0..3
    const int nt = blockIdx.y;          // 0..781
    const int tid = threadIdx.x;
    const int lane = tid & 31, w = tid >> 5;
    const int wm = (w >> 2) * 64;
    const int wn = (w & 3) * 32;
    const uint32_t sb = smem_u32(dsm);

    float acc[4][4][4];
#pragma unroll
    for (int i = 0; i < 4; i++)
#pragma unroll
        for (int j = 0; j < 4; j++)
#pragma unroll
            for (int q = 0; q < 4; q++) acc[i][j][q] = 0.f;

    // ldmatrix lane geometry
    const int rA = wm + ((lane >> 3) & 1) * 8 + (lane & 7);   // + mf*16
    const int a_c4 = lane >> 4;
    const int rB = wn + ((lane >> 4) & 1) * 8 + (lane & 7);   // + nf2*16
    const int b_c4 = (lane >> 3) & 1;

    uint32_t aAddr[4], bAddr[2];   // row-dependent parts (per stage add base+chunk xor)
    int rxA[4], rxB[2];
#pragma unroll
    for (int mf = 0; mf < 4; mf++) {
        int r = rA + mf * 16;
        aAddr[mf] = r * 64;
        rxA[mf] = (r >> 1) & 3;
    }
#pragma unroll
    for (int nf2 = 0; nf2 < 2; nf2++) {
        int r = rB + nf2 * 16;
        bAddr[nf2] = r * 64;
        rxB[nf2] = (r >> 1) & 3;
    }

    issue_stage(sb, 0, mg, nt, tid);
    issue_stage(sb, 1, mg, nt, tid);

#pragma unroll 1
    for (int c = 0; c < NCH; c++) {
        if (c < NCH - 2)
            asm volatile("cp.async.wait_group 1;" ::: "memory");
        else
            asm volatile("cp.async.wait_group 0;" ::: "memory");
        __syncthreads();
        if (c + 2 < NCH) issue_stage(sb, c + 2, mg, nt, tid);

        const uint32_t st = sb + (c % NSTAGE) * STAGE_BYTES;
#pragma unroll
        for (int kh = 0; kh < 2; kh++) {
            uint32_t Ah[4][4], Al[4][4], Bh[2][4], Bl[2][4];
#pragma unroll
            for (int mf = 0; mf < 4; mf++)
                ldsm4(Ah[mf], st + OFF_AH + aAddr[mf] + (((kh * 2 + a_c4) ^ rxA[mf]) << 4));
#pragma unroll
            for (int nf2 = 0; nf2 < 2; nf2++)
                ldsm4(Bh[nf2], st + OFF_BH + bAddr[nf2] + (((kh * 2 + b_c4) ^ rxB[nf2]) << 4));
#pragma unroll
            for (int mf = 0; mf < 4; mf++)
#pragma unroll
                for (int nf = 0; nf < 4; nf++)
                    mma16816(acc[mf][nf], Ah[mf], &Bh[nf >> 1][(nf & 1) * 2]);
#pragma unroll
            for (int nf2 = 0; nf2 < 2; nf2++)
                ldsm4(Bl[nf2], st + OFF_BL + bAddr[nf2] + (((kh * 2 + b_c4) ^ rxB[nf2]) << 4));
#pragma unroll
            for (int mf = 0; mf < 4; mf++)
#pragma unroll
                for (int nf = 0; nf < 4; nf++)
                    mma16816(acc[mf][nf], Ah[mf], &Bl[nf >> 1][(nf & 1) * 2]);
#pragma unroll
            for (int mf = 0; mf < 4; mf++)
                ldsm4(Al[mf], st + OFF_AL + aAddr[mf] + (((kh * 2 + a_c4) ^ rxA[mf]) << 4));
#pragma unroll
            for (int mf = 0; mf < 4; mf++)
#pragma unroll
                for (int nf = 0; nf < 4; nf++)
                    mma16816(acc[mf][nf], Al[mf], &Bh[nf >> 1][(nf & 1) * 2]);
        }
    }

    // Epilogue
    const int mrow = mg * 128 + wm + (lane >> 2);
    const int ncol = nt * 128 + wn + (lane & 3) * 2;
#pragma unroll
    for (int mf = 0; mf < 4; mf++) {
#pragma unroll
        for (int nf = 0; nf < 4; nf++) {
            int n = ncol + nf * 8;
            if (n < N_FEATS) {
                size_t m = (size_t)(mrow + mf * 16);
                *(float2*)(g_sim + m * N_FEATS + n) =
                    make_float2(acc[mf][nf][0], acc[mf][nf][1]);
                *(float2*)(g_sim + (m + 8) * N_FEATS + n) =
                    make_float2(acc[mf][nf][2], acc[mf][nf][3]);
            }
        }
    }
}

// ---------------------------------------------------------------------------
// Top-10 per row (tie-break: lower index)
// ---------------------------------------------------------------------------
static __device__ __forceinline__ bool better(float v, int j, float v2, int j2) {
    return v > v2 || (v == v2 && j < j2);
}
static __device__ __forceinline__ void insert10(float (&tv)[TOPK], int (&ti)[TOPK],
                                                float v, int j) {
    if (!better(v, j, tv[TOPK - 1], ti[TOPK - 1])) return;
    bool b[TOPK];
#pragma unroll
    for (int p = 0; p < TOPK; p++) b[p] = better(v, j, tv[p], ti[p]);
#pragma unroll
    for (int p = TOPK - 1; p >= 1; p--) {
        if (b[p]) {
            if (b[p - 1]) { tv[p] = tv[p - 1]; ti[p] = ti[p - 1]; }
            else          { tv[p] = v;         ti[p] = j;         }
        }
    }
    if (b[0]) { tv[0] = v; ti[0] = j; }
}

#define TK_THREADS 256
__global__ void __launch_bounds__(TK_THREADS) topk_kernel() {
    const int row = blockIdx.x;
    const float* s = g_sim + (size_t)row * N_FEATS;
    const int tid = threadIdx.x;

    float tv[TOPK]; int ti[TOPK];
#pragma unroll
    for (int p = 0; p < TOPK; p++) { tv[p] = -__int_as_float(0x7f800000); ti[p] = 0x7fffffff; }

    for (int j = tid; j < N_FEATS; j += TK_THREADS)
        insert10(tv, ti, s[j], j);

    __shared__ float sv[TK_THREADS * TOPK];
    __shared__ int   si[TK_THREADS * TOPK];
    __shared__ float sv2[32 * TOPK];
    __shared__ int   si2[32 * TOPK];
#pragma unroll
    for (int p = 0; p < TOPK; p++) { sv[tid * TOPK + p] = tv[p]; si[tid * TOPK + p] = ti[p]; }
    __syncthreads();

    if (tid < 32) {
#pragma unroll
        for (int p = 0; p < TOPK; p++) { tv[p] = -__int_as_float(0x7f800000); ti[p] = 0x7fffffff; }
        const int per = (TK_THREADS * TOPK) / 32;
        for (int c = tid * per; c < (tid + 1) * per; c++)
            insert10(tv, ti, sv[c], si[c]);
#pragma unroll
        for (int p = 0; p < TOPK; p++) { sv2[tid * TOPK + p] = tv[p]; si2[tid * TOPK + p] = ti[p]; }
    }
    __syncthreads();

    if (tid == 0) {
#pragma unroll
        for (int p = 0; p < TOPK; p++) { tv[p] = -__int_as_float(0x7f800000); ti[p] = 0x7fffffff; }
        for (int c = 0; c < 32 * TOPK; c++)
            insert10(tv, ti, sv2[c], si2[c]);
#pragma unroll
        for (int p = 0; p < TOPK; p++) g_topk[row * TOPK + p] = ti[p];
    }
}

// ---------------------------------------------------------------------------
__global__ void zero_kernel(float4* __restrict__ out, int n4) {
    int i = blockIdx.x * blockDim.x + threadIdx.x;
    if (i < n4) out[i] = make_float4(0.f, 0.f, 0.f, 0.f);
}
__global__ void scatter_kernel(const int* __restrict__ y, float* __restrict__ out) {
    int row = blockIdx.x;
    int t = threadIdx.x;
    if (t < TOPK) {
        int idx = g_topk[row * TOPK + t];
        int cls = y[idx];
        out[(size_t)row * C_CLS + cls] = 1.0f;
    }
}

// ---------------------------------------------------------------------------
extern "C" void kernel_launch(void* const* d_in, const int* in_sizes, int n_in,
                              void* d_out, int out_size) {
    const float* y_pred = (const float*)d_in[0];  // [512, 512]
    const float* feats  = (const float*)d_in[1];  // [100000, 512]
    const int*   y      = (const int*)d_in[2];    // [100000]
    float* out = (float*)d_out;                   // [512, 1854]

    // Resolve device-global addresses (host side, graph-capturable: no allocs)
    static __nv_bfloat16 *p_fhi = nullptr, *p_flo = nullptr, *p_ahi = nullptr, *p_alo = nullptr;
    if (!p_fhi) {
        cudaGetSymbolAddress((void**)&p_fhi, g_fhi);
        cudaGetSymbolAddress((void**)&p_flo, g_flo);
        cudaGetSymbolAddress((void**)&p_ahi, g_ahi);
        cudaGetSymbolAddress((void**)&p_alo, g_alo);
    }

    cvt_kernel<<<(N_FEATS * D_DIM / 4 + 255) / 256, 256>>>(feats, p_fhi, p_flo,
                                                           N_FEATS * D_DIM / 4);
    cvt_kernel<<<(B_ROWS * D_DIM / 4 + 255) / 256, 256>>>(y_pred, p_ahi, p_alo,
                                                          B_ROWS * D_DIM / 4);

    cudaFuncSetAttribute(gemm_hmma, cudaFuncAttributeMaxDynamicSharedMemorySize, SMEM_TOTAL);
    dim3 ggrid(4, (N_FEATS + 127) / 128);  // m fastest -> B tile L2 reuse x4
    gemm_hmma<<<ggrid, 256, SMEM_TOTAL>>>();

    topk_kernel<<<B_ROWS, TK_THREADS>>>();

    int n4 = out_size / 4;
    zero_kernel<<<(n4 + 255) / 256, 256>>>((float4*)out, n4);
    scatter_kernel<<<B_ROWS, 32>>>(y, out);
}

// round 5
// speedup vs baseline: 2.7768x; 1.3422x over previous
#include <cuda_runtime.h>
#include <cuda_bf16.h>
#include <cstdint>

#define N_FEATS 100000
#define B_ROWS  512
#define D_DIM   512
#define C_CLS   1854
#define TOPK    10

#define KC      32
#define NCH     (D_DIM / KC)
#define NSTAGE  3
#define STAGE_BYTES 32768
#define SMEM_TOTAL (NSTAGE * STAGE_BYTES)   // 96 KB -> 2 CTAs/SM
#define OFF_AH 0
#define OFF_AL 8192
#define OFF_BH 16384
#define OFF_BL 24576

__device__ float g_sim[(size_t)B_ROWS * N_FEATS];          // 204.8 MB
__device__ __nv_bfloat16 g_fhi[(size_t)N_FEATS * D_DIM];   // 102.4 MB
__device__ __nv_bfloat16 g_flo[(size_t)N_FEATS * D_DIM];   // 102.4 MB
__device__ __nv_bfloat16 g_ahi[B_ROWS * D_DIM];
__device__ __nv_bfloat16 g_alo[B_ROWS * D_DIM];
__device__ int g_topk[B_ROWS * TOPK];

static __device__ __forceinline__ uint32_t smem_u32(const void* p) {
    uint32_t a;
    asm("{ .reg .u64 t; cvta.to.shared.u64 t, %1; cvt.u32.u64 %0, t; }" : "=r"(a) : "l"(p));
    return a;
}
static __device__ __forceinline__ void ldsm4(uint32_t (&r)[4], uint32_t addr) {
    asm volatile("ldmatrix.sync.aligned.m8n8.x4.shared.b16 {%0,%1,%2,%3}, [%4];"
                 : "=r"(r[0]), "=r"(r[1]), "=r"(r[2]), "=r"(r[3]) : "r"(addr));
}
static __device__ __forceinline__ void mma16816(float (&d)[4], const uint32_t (&a)[4],
                                                const uint32_t* b) {
    asm volatile(
        "mma.sync.aligned.m16n8k16.row.col.f32.bf16.bf16.f32 "
        "{%0,%1,%2,%3}, {%4,%5,%6,%7}, {%8,%9}, {%0,%1,%2,%3};"
        : "+f"(d[0]), "+f"(d[1]), "+f"(d[2]), "+f"(d[3])
        : "r"(a[0]), "r"(a[1]), "r"(a[2]), "r"(a[3]), "r"(b[0]), "r"(b[1]));
}
static __device__ __forceinline__ void cp16(uint32_t dst, const void* src, uint32_t sz) {
    asm volatile("cp.async.cg.shared.global [%0], [%1], 16, %2;"
                 :: "r"(dst), "l"(src), "r"(sz) : "memory");
}

// ---------------------------------------------------------------------------
// Pre-convert: fp32 -> (bf16 hi, bf16 lo)
// ---------------------------------------------------------------------------
__global__ void cvt_kernel(const float* __restrict__ src, __nv_bfloat16* __restrict__ hi,
                           __nv_bfloat16* __restrict__ lo, int n4) {
    int i = blockIdx.x * blockDim.x + threadIdx.x;
    if (i >= n4) return;
    float4 v = ((const float4*)src)[i];
    __nv_bfloat162 h01 = __floats2bfloat162_rn(v.x, v.y);
    __nv_bfloat162 h23 = __floats2bfloat162_rn(v.z, v.w);
    __nv_bfloat162 l01 = __floats2bfloat162_rn(v.x - __low2float(h01), v.y - __high2float(h01));
    __nv_bfloat162 l23 = __floats2bfloat162_rn(v.z - __low2float(h23), v.w - __high2float(h23));
    ((uint2*)hi)[i] = make_uint2(*(uint32_t*)&h01, *(uint32_t*)&h23);
    ((uint2*)lo)[i] = make_uint2(*(uint32_t*)&l01, *(uint32_t*)&l23);
}

// ---------------------------------------------------------------------------
// GEMM mainloop: cp.async 3-stage, split-bf16 HMMA (hh + hl + lh)
// ---------------------------------------------------------------------------
extern __shared__ char dsm[];

static __device__ __forceinline__ void issue_stage(uint32_t sbase, int c, int mg, int nt,
                                                   int tid) {
    const uint32_t stage = sbase + (c % NSTAGE) * STAGE_BYTES;
#pragma unroll
    for (int j = 0; j < 8; j++) {
        int id = tid + j * 256;
        int mat = id >> 9;          // 0:Ah 1:Al 2:Bh 3:Bl
        int rem = id & 511;
        int row = rem >> 2;
        int cc = rem & 3;
        uint32_t dst = stage + mat * 8192 + row * 64 + ((cc ^ ((row >> 1) & 3)) << 4);
        uint32_t sz = 16;
        const __nv_bfloat16* src;
        if (mat < 2) {
            src = (mat == 0 ? g_ahi : g_alo) + (size_t)(mg * 128 + row) * D_DIM + c * KC + cc * 8;
        } else {
            int n = nt * 128 + row;
            if (n >= N_FEATS) { sz = 0; n = 0; }
            src = (mat == 2 ? g_fhi : g_flo) + (size_t)n * D_DIM + c * KC + cc * 8;
        }
        cp16(dst, src, sz);
    }
    asm volatile("cp.async.commit_group;" ::: "memory");
}

__global__ void __launch_bounds__(256, 2) gemm_hmma(void) {
    const int mg = blockIdx.x;
    const int nt = blockIdx.y;
    const int tid = threadIdx.x;
    const int lane = tid & 31, w = tid >> 5;
    const int wm = (w >> 2) * 64;
    const int wn = (w & 3) * 32;
    const uint32_t sb = smem_u32(dsm);

    float acc[4][4][4];
#pragma unroll
    for (int i = 0; i < 4; i++)
#pragma unroll
        for (int j = 0; j < 4; j++)
#pragma unroll
            for (int q = 0; q < 4; q++) acc[i][j][q] = 0.f;

    const int rA = wm + ((lane >> 3) & 1) * 8 + (lane & 7);
    const int a_c4 = lane >> 4;
    const int rB = wn + ((lane >> 4) & 1) * 8 + (lane & 7);
    const int b_c4 = (lane >> 3) & 1;

    uint32_t aAddr[4], bAddr[2];
    int rxA[4], rxB[2];
#pragma unroll
    for (int mf = 0; mf < 4; mf++) {
        int r = rA + mf * 16;
        aAddr[mf] = r * 64;
        rxA[mf] = (r >> 1) & 3;
    }
#pragma unroll
    for (int nf2 = 0; nf2 < 2; nf2++) {
        int r = rB + nf2 * 16;
        bAddr[nf2] = r * 64;
        rxB[nf2] = (r >> 1) & 3;
    }

    issue_stage(sb, 0, mg, nt, tid);
    issue_stage(sb, 1, mg, nt, tid);

#pragma unroll 1
    for (int c = 0; c < NCH; c++) {
        if (c < NCH - 2)
            asm volatile("cp.async.wait_group 1;" ::: "memory");
        else
            asm volatile("cp.async.wait_group 0;" ::: "memory");
        __syncthreads();
        if (c + 2 < NCH) issue_stage(sb, c + 2, mg, nt, tid);

        const uint32_t st = sb + (c % NSTAGE) * STAGE_BYTES;
#pragma unroll
        for (int kh = 0; kh < 2; kh++) {
            uint32_t Ah[4][4], Al[4][4], Bh[2][4], Bl[2][4];
#pragma unroll
            for (int mf = 0; mf < 4; mf++)
                ldsm4(Ah[mf], st + OFF_AH + aAddr[mf] + (((kh * 2 + a_c4) ^ rxA[mf]) << 4));
#pragma unroll
            for (int nf2 = 0; nf2 < 2; nf2++)
                ldsm4(Bh[nf2], st + OFF_BH + bAddr[nf2] + (((kh * 2 + b_c4) ^ rxB[nf2]) << 4));
#pragma unroll
            for (int mf = 0; mf < 4; mf++)
#pragma unroll
                for (int nf = 0; nf < 4; nf++)
                    mma16816(acc[mf][nf], Ah[mf], &Bh[nf >> 1][(nf & 1) * 2]);
#pragma unroll
            for (int nf2 = 0; nf2 < 2; nf2++)
                ldsm4(Bl[nf2], st + OFF_BL + bAddr[nf2] + (((kh * 2 + b_c4) ^ rxB[nf2]) << 4));
#pragma unroll
            for (int mf = 0; mf < 4; mf++)
#pragma unroll
                for (int nf = 0; nf < 4; nf++)
                    mma16816(acc[mf][nf], Ah[mf], &Bl[nf >> 1][(nf & 1) * 2]);
#pragma unroll
            for (int mf = 0; mf < 4; mf++)
                ldsm4(Al[mf], st + OFF_AL + aAddr[mf] + (((kh * 2 + a_c4) ^ rxA[mf]) << 4));
#pragma unroll
            for (int mf = 0; mf < 4; mf++)
#pragma unroll
                for (int nf = 0; nf < 4; nf++)
                    mma16816(acc[mf][nf], Al[mf], &Bh[nf >> 1][(nf & 1) * 2]);
        }
    }

    const int mrow = mg * 128 + wm + (lane >> 2);
    const int ncol = nt * 128 + wn + (lane & 3) * 2;
#pragma unroll
    for (int mf = 0; mf < 4; mf++) {
#pragma unroll
        for (int nf = 0; nf < 4; nf++) {
            int n = ncol + nf * 8;
            if (n < N_FEATS) {
                size_t m = (size_t)(mrow + mf * 16);
                *(float2*)(g_sim + m * N_FEATS + n) =
                    make_float2(acc[mf][nf][0], acc[mf][nf][1]);
                *(float2*)(g_sim + (m + 8) * N_FEATS + n) =
                    make_float2(acc[mf][nf][2], acc[mf][nf][3]);
            }
        }
    }
}

// ---------------------------------------------------------------------------
// Top-10: sample -> threshold -> filter -> select
// ---------------------------------------------------------------------------
static __device__ __forceinline__ bool better(float v, int j, float v2, int j2) {
    return v > v2 || (v == v2 && j < j2);
}
static __device__ __forceinline__ void insert10(float (&tv)[TOPK], int (&ti)[TOPK],
                                                float v, int j) {
    if (!better(v, j, tv[TOPK - 1], ti[TOPK - 1])) return;
    bool b[TOPK];
#pragma unroll
    for (int p = 0; p < TOPK; p++) b[p] = better(v, j, tv[p], ti[p]);
#pragma unroll
    for (int p = TOPK - 1; p >= 1; p--) {
        if (b[p]) {
            if (b[p - 1]) { tv[p] = tv[p - 1]; ti[p] = ti[p - 1]; }
            else          { tv[p] = v;         ti[p] = j;         }
        }
    }
    if (b[0]) { tv[0] = v; ti[0] = j; }
}

#define TK_THREADS 256
#define SAMPLE 2048
#define CAP 2048

__global__ void __launch_bounds__(TK_THREADS) topk_kernel() {
    const int row = blockIdx.x;
    const float* s = g_sim + (size_t)row * N_FEATS;
    const int tid = threadIdx.x;

    __shared__ float sv[TK_THREADS * TOPK];
    __shared__ int   si[TK_THREADS * TOPK];
    __shared__ float sv2[32 * TOPK];
    __shared__ int   si2[32 * TOPK];
    __shared__ float cv[CAP];
    __shared__ int   ci[CAP];
    __shared__ float s_thresh;
    __shared__ int   s_cnt;

    const float NEG = -__int_as_float(0x7f800000);
    float tv[TOPK]; int ti[TOPK];

    // ---- Phase A: threshold = 10th largest of first SAMPLE elements ----
#pragma unroll
    for (int p = 0; p < TOPK; p++) { tv[p] = NEG; ti[p] = 0x7fffffff; }
    for (int j = tid; j < SAMPLE; j += TK_THREADS)
        insert10(tv, ti, s[j], j);
#pragma unroll
    for (int p = 0; p < TOPK; p++) { sv[tid * TOPK + p] = tv[p]; si[tid * TOPK + p] = ti[p]; }
    if (tid == 0) s_cnt = 0;
    __syncthreads();

    if (tid < 32) {
#pragma unroll
        for (int p = 0; p < TOPK; p++) { tv[p] = NEG; ti[p] = 0x7fffffff; }
        for (int c = tid * 80; c < (tid + 1) * 80; c++)
            insert10(tv, ti, sv[c], si[c]);
#pragma unroll
        for (int p = 0; p < TOPK; p++) { sv2[tid * TOPK + p] = tv[p]; si2[tid * TOPK + p] = ti[p]; }
    }
    __syncthreads();
    if (tid == 0) {
#pragma unroll
        for (int p = 0; p < TOPK; p++) { tv[p] = NEG; ti[p] = 0x7fffffff; }
        for (int c = 0; c < 32 * TOPK; c++)
            insert10(tv, ti, sv2[c], si2[c]);
        s_thresh = tv[TOPK - 1];
    }
    __syncthreads();

    // ---- Phase B: filter whole row, collect v >= t ----
    const float t = s_thresh;
    const float4* s4 = (const float4*)s;
    for (int j4 = tid; j4 < N_FEATS / 4; j4 += TK_THREADS) {
        float4 v = s4[j4];
        if (v.x >= t || v.y >= t || v.z >= t || v.w >= t) {
            int j = j4 * 4;
            if (v.x >= t) { int p = atomicAdd(&s_cnt, 1); if (p < CAP) { cv[p] = v.x; ci[p] = j; } }
            if (v.y >= t) { int p = atomicAdd(&s_cnt, 1); if (p < CAP) { cv[p] = v.y; ci[p] = j + 1; } }
            if (v.z >= t) { int p = atomicAdd(&s_cnt, 1); if (p < CAP) { cv[p] = v.z; ci[p] = j + 2; } }
            if (v.w >= t) { int p = atomicAdd(&s_cnt, 1); if (p < CAP) { cv[p] = v.w; ci[p] = j + 3; } }
        }
    }
    __syncthreads();

    const int cnt = s_cnt;
#pragma unroll
    for (int p = 0; p < TOPK; p++) { tv[p] = NEG; ti[p] = 0x7fffffff; }

    if (cnt <= CAP) {
        // ---- Phase C: exact top-10 of candidates ----
        for (int c = tid; c < cnt; c += TK_THREADS)
            insert10(tv, ti, cv[c], ci[c]);
    } else {
        // Fallback (effectively unreachable for this data; correctness-safe)
        for (int j = tid; j < N_FEATS; j += TK_THREADS)
            insert10(tv, ti, s[j], j);
    }
#pragma unroll
    for (int p = 0; p < TOPK; p++) { sv[tid * TOPK + p] = tv[p]; si[tid * TOPK + p] = ti[p]; }
    __syncthreads();

    if (tid < 32) {
#pragma unroll
        for (int p = 0; p < TOPK; p++) { tv[p] = NEG; ti[p] = 0x7fffffff; }
        for (int c = tid * 80; c < (tid + 1) * 80; c++)
            insert10(tv, ti, sv[c], si[c]);
#pragma unroll
        for (int p = 0; p < TOPK; p++) { sv2[tid * TOPK + p] = tv[p]; si2[tid * TOPK + p] = ti[p]; }
    }
    __syncthreads();
    if (tid == 0) {
#pragma unroll
        for (int p = 0; p < TOPK; p++) { tv[p] = NEG; ti[p] = 0x7fffffff; }
        for (int c = 0; c < 32 * TOPK; c++)
            insert10(tv, ti, sv2[c], si2[c]);
#pragma unroll
        for (int p = 0; p < TOPK; p++) g_topk[row * TOPK + p] = ti[p];
    }
}

// ---------------------------------------------------------------------------
__global__ void zero_kernel(float4* __restrict__ out, int n4) {
    int i = blockIdx.x * blockDim.x + threadIdx.x;
    if (i < n4) out[i] = make_float4(0.f, 0.f, 0.f, 0.f);
}
__global__ void scatter_kernel(const int* __restrict__ y, float* __restrict__ out) {
    int row = blockIdx.x;
    int t = threadIdx.x;
    if (t < TOPK) {
        int idx = g_topk[row * TOPK + t];
        int cls = y[idx];
        out[(size_t)row * C_CLS + cls] = 1.0f;
    }
}

// ---------------------------------------------------------------------------
extern "C" void kernel_launch(void* const* d_in, const int* in_sizes, int n_in,
                              void* d_out, int out_size) {
    const float* y_pred = (const float*)d_in[0];
    const float* feats  = (const float*)d_in[1];
    const int*   y      = (const int*)d_in[2];
    float* out = (float*)d_out;

    static __nv_bfloat16 *p_fhi = nullptr, *p_flo = nullptr, *p_ahi = nullptr, *p_alo = nullptr;
    if (!p_fhi) {
        cudaGetSymbolAddress((void**)&p_fhi, g_fhi);
        cudaGetSymbolAddress((void**)&p_flo, g_flo);
        cudaGetSymbolAddress((void**)&p_ahi, g_ahi);
        cudaGetSymbolAddress((void**)&p_alo, g_alo);
    }

    cvt_kernel<<<(N_FEATS * D_DIM / 4 + 255) / 256, 256>>>(feats, p_fhi, p_flo,
                                                           N_FEATS * D_DIM / 4);
    cvt_kernel<<<(B_ROWS * D_DIM / 4 + 255) / 256, 256>>>(y_pred, p_ahi, p_alo,
                                                          B_ROWS * D_DIM / 4);

    cudaFuncSetAttribute(gemm_hmma, cudaFuncAttributeMaxDynamicSharedMemorySize, SMEM_TOTAL);
    dim3 ggrid(4, (N_FEATS + 127) / 128);
    gemm_hmma<<<ggrid, 256, SMEM_TOTAL>>>();

    topk_kernel<<<B_ROWS, TK_THREADS>>>();

    int n4 = out_size / 4;
    zero_kernel<<<(n4 + 255) / 256, 256>>>((float4*)out, n4);
    scatter_kernel<<<B_ROWS, 32>>>(y, out);
}